// round 10
// baseline (speedup 1.0000x reference)
#include <cuda_runtime.h>
#include <math.h>

// Problem constants
#define BB   64
#define TT   256
#define DD   1024
#define HH   1024
#define G4   4096      // 4*H
#define MROWS (BB*TT)  // 16384
#define NBLK 128u      // persistent grid size (<= SM count, all co-resident)

// Scratch (static device allocations — allowed; no cudaMalloc anywhere)
__device__ float g_xz[2][MROWS][G4];       // input projections, fwd/bwd (536 MB)
__device__ float g_h[2][2][BB][HH];        // h state, [buffer][dir][b][j]
__device__ unsigned g_bar;                 // grid barrier counter

// ---------------------------------------------------------------------------
// Packed f32x2 helpers: one FFMA2 = 2 fp32 MACs per fma-pipe issue.
// ---------------------------------------------------------------------------
typedef unsigned long long u64;

__device__ __forceinline__ u64 fma2_(u64 a, u64 b, u64 c) {
    u64 d;
    asm("fma.rn.f32x2 %0, %1, %2, %3;" : "=l"(d) : "l"(a), "l"(b), "l"(c));
    return d;
}
__device__ __forceinline__ u64 add2_(u64 a, u64 b) {
    u64 d;
    asm("add.rn.f32x2 %0, %1, %2;" : "=l"(d) : "l"(a), "l"(b));
    return d;
}
__device__ __forceinline__ u64 pack2_(float v) {   // (v, v)
    u64 d;
    asm("mov.b64 %0, {%1, %1};" : "=l"(d) : "r"(__float_as_uint(v)));
    return d;
}
__device__ __forceinline__ void unpack2_(u64 v, float& lo, float& hi) {
    asm("mov.b64 {%0, %1}, %2;" : "=f"(lo), "=f"(hi) : "l"(v));
}
__device__ __forceinline__ double ull_as_d(u64 v) {
    return __longlong_as_double((long long)v);
}

// ---------------------------------------------------------------------------
// Reset the grid-barrier counter (fresh on every graph replay).
// ---------------------------------------------------------------------------
__global__ void reset_kernel() { g_bar = 0u; }

// ---------------------------------------------------------------------------
// Grid-wide barrier for a fully co-resident grid (CG grid.sync pattern).
// ---------------------------------------------------------------------------
__device__ __forceinline__ void grid_barrier(unsigned target) {
    __syncthreads();
    if (threadIdx.x == 0) {
        unsigned* p = &g_bar;
        asm volatile("red.release.gpu.global.add.u32 [%0], 1;" :: "l"(p) : "memory");
        unsigned v;
        for (;;) {
            asm volatile("ld.acquire.gpu.global.u32 %0, [%1];" : "=r"(v) : "l"(p) : "memory");
            if (v >= target) break;
            __nanosleep(32);
        }
    }
    __syncthreads();
}

// ---------------------------------------------------------------------------
// Input projection (R8-known-good): FFMA2, double-buffered, single barrier,
// streaming g_xz stores. grid = (64,128): x = dir*32+ntile, y = mtile.
// ---------------------------------------------------------------------------
__global__ __launch_bounds__(256)
void input_gemm_kernel(const float* __restrict__ x,
                       const float* __restrict__ Wf, const float* __restrict__ bf,
                       const float* __restrict__ Wb, const float* __restrict__ bb)
{
    const int dir = blockIdx.x >> 5;
    const int nt  = blockIdx.x & 31;
    const int m0  = blockIdx.y * 128;
    const int n0  = nt * 128;
    const float* __restrict__ W    = dir ? Wb : Wf;
    const float* __restrict__ bias = dir ? bb : bf;

    __shared__ float As[2][8][128];
    __shared__ float Bs[2][8][128];

    const int tid = threadIdx.x;
    const int tm = tid >> 4;
    const int tn = tid & 15;

    const int arow  = tid >> 1;
    const int acol4 = (tid & 1) * 4;
    const int brow  = tid >> 5;
    const int bcol  = (tid & 31) * 4;

    u64 acc2[8][4];
    #pragma unroll
    for (int i = 0; i < 8; i++)
        #pragma unroll
        for (int p = 0; p < 4; p++) acc2[i][p] = 0ull;

    const float* __restrict__ aptr = x + (size_t)(m0 + arow) * DD + acol4;
    const float* __restrict__ bptr = W + (size_t)brow * G4 + n0 + bcol;

    float4 av = *(const float4*)(aptr);
    float4 bv = *(const float4*)(bptr);

    const int NCHUNK = DD / 8;  // 128
    for (int c = 0; c < NCHUNK; c++) {
        const int buf = c & 1;
        As[buf][acol4 + 0][arow] = av.x;
        As[buf][acol4 + 1][arow] = av.y;
        As[buf][acol4 + 2][arow] = av.z;
        As[buf][acol4 + 3][arow] = av.w;
        *(float4*)&Bs[buf][brow][bcol] = bv;
        __syncthreads();

        if (c + 1 < NCHUNK) {
            const int k0 = (c + 1) * 8;
            av = *(const float4*)(aptr + k0);
            bv = *(const float4*)(bptr + (size_t)k0 * G4);
        }

        #pragma unroll
        for (int k = 0; k < 8; k++) {
            float4 a0 = *(const float4*)&As[buf][k][tm * 8];
            float4 a1 = *(const float4*)&As[buf][k][tm * 8 + 4];
            ulonglong2 b0 = *(const ulonglong2*)&Bs[buf][k][tn * 8];
            ulonglong2 b1 = *(const ulonglong2*)&Bs[buf][k][tn * 8 + 4];
            u64 bp0 = b0.x, bp1 = b0.y, bp2 = b1.x, bp3 = b1.y;
            float ra[8] = {a0.x, a0.y, a0.z, a0.w, a1.x, a1.y, a1.z, a1.w};
            #pragma unroll
            for (int i = 0; i < 8; i++) {
                u64 ad = pack2_(ra[i]);
                acc2[i][0] = fma2_(ad, bp0, acc2[i][0]);
                acc2[i][1] = fma2_(ad, bp1, acc2[i][1]);
                acc2[i][2] = fma2_(ad, bp2, acc2[i][2]);
                acc2[i][3] = fma2_(ad, bp3, acc2[i][3]);
            }
        }
    }

    union { float4 f; ulonglong2 u; } bv0, bv1;
    bv0.f = *(const float4*)&bias[n0 + tn * 8];
    bv1.f = *(const float4*)&bias[n0 + tn * 8 + 4];
    u64 bias2[4] = {bv0.u.x, bv0.u.y, bv1.u.x, bv1.u.y};

    #pragma unroll
    for (int i = 0; i < 8; i++) {
        const int row = m0 + tm * 8 + i;
        float* dst = &g_xz[dir][row][n0 + tn * 8];
        double2 o0, o1;
        o0.x = ull_as_d(add2_(acc2[i][0], bias2[0]));
        o0.y = ull_as_d(add2_(acc2[i][1], bias2[1]));
        o1.x = ull_as_d(add2_(acc2[i][2], bias2[2]));
        o1.y = ull_as_d(add2_(acc2[i][3], bias2[3]));
        __stcs((double2*)&dst[0], o0);
        __stcs((double2*)&dst[4], o1);
    }
}

// ---------------------------------------------------------------------------
// Persistent BiLSTM recurrence. 128 blocks x 256 threads, all 256 steps.
// R10: j-pair FFMA2 packing. Thread (bm=tid>>3, jp=tid&7) owns b rows
// {2bm,2bm+1} x j cols {j0+2jp, j0+2jp+1} x 4 gates.
// U pairs are native adjacent floats -> SMEM u64 arrays UsA (gates i,f) and
// UsB (gates g,o); zero pack instructions for U, conflict-free 1-wavefront
// LDS.128 reads. Only h is broadcast-packed (2 pack2_ per k).
// Inner loop/warp/k: 8 FFMA2 + 3 LDS + ~4 MOV = 15 slots <= 16-slot budget
// -> FFMA2-pipe bound (32 cyc/k/SMSP).
// ---------------------------------------------------------------------------
__device__ __forceinline__ float sigmoidf_(float v) {
    return 1.0f / (1.0f + __expf(-v));
}

__global__ __launch_bounds__(256, 1)
void persistent_lstm_kernel(const float* __restrict__ Uf,
                            const float* __restrict__ Ub,
                            float* __restrict__ out)
{
    const int bx  = blockIdx.x;
    const int dir = bx >> 6;
    const int j0  = (bx & 63) * 16;
    const float* __restrict__ U = dir ? Ub : Uf;

    __shared__ float Hs[2][16][64];        // [buf][k][b]
    __shared__ u64   UsA[2][16][8][2];     // [buf][k][jp][gate i,f]  native j-pairs
    __shared__ u64   UsB[2][16][8][2];     // [buf][k][jp][gate g,o]

    const int tid = threadIdx.x;
    const int bm = tid >> 3;           // 0..31 -> b rows 2bm, 2bm+1
    const int jp = tid & 7;            // 0..7  -> j cols j0+2jp, +1
    const int je = j0 + 2 * jp;        // even j column

    // loader indices
    const int hb  = tid >> 2;          // 0..63
    const int hk4 = (tid & 3) * 4;     // 0,4,8,12
    const int uk   = tid >> 4;         // 0..15 (k within chunk)
    const int ug   = (tid >> 2) & 3;   // gate 0..3
    const int ujp2 = tid & 3;          // 0..3 -> j block of 4

    const float* __restrict__ ubase = U + (size_t)uk * G4 + ug * HH + j0 + 4 * ujp2;
    const float* __restrict__ hsrc0 = &g_h[0][dir][hb][hk4];
    const float* __restrict__ hsrc1 = &g_h[1][dir][hb][hk4];

    // step-invariant U chunk-0 register copy
    const float4 ru0 = *(const float4*)(ubase);

    // ---- phase 0: zero the s=0 read buffer for this block's slice; c -> regs
    const float2 fz = make_float2(0.0f, 0.0f);
    #pragma unroll
    for (int r = 0; r < 2; r++)
        __stcg((float2*)&g_h[0][dir][2 * bm + r][je], fz);
    float c_reg[2][2] = {{0.0f, 0.0f}, {0.0f, 0.0f}};

    grid_barrier(NBLK);

    // ---- 256 timesteps
    for (int s = 0; s < TT; s++) {
        const int t    = dir ? (TT - 1 - s) : s;
        const int rb   = s & 1;
        const int wbuf = rb ^ 1;
        const float* __restrict__ hsrc = rb ? hsrc1 : hsrc0;

        // xz for the epilogue: float2 per (row, gate), streaming
        float2 xzv[2][4];
        #pragma unroll
        for (int r = 0; r < 2; r++) {
            const int b = 2 * bm + r;
            const float* xz = &g_xz[dir][(size_t)b * TT + t][je];
            xzv[r][0] = __ldcs((const float2*)(xz));
            xzv[r][1] = __ldcs((const float2*)(xz + HH));
            xzv[r][2] = __ldcs((const float2*)(xz + 2 * HH));
            xzv[r][3] = __ldcs((const float2*)(xz + 3 * HH));
        }

        u64 acc[2][4];   // [b-row][gate], each packs (j_even, j_odd)
        #pragma unroll
        for (int r = 0; r < 2; r++)
            #pragma unroll
            for (int q = 0; q < 4; q++) acc[r][q] = 0ull;

        float4 rh = __ldcg((const float4*)hsrc);
        float4 ru = ru0;

        const int NCHUNK = HH / 16;  // 64
        for (int c = 0; c < NCHUNK; c++) {
            const int buf = c & 1;
            Hs[buf][hk4 + 0][hb] = rh.x;
            Hs[buf][hk4 + 1][hb] = rh.y;
            Hs[buf][hk4 + 2][hb] = rh.z;
            Hs[buf][hk4 + 3][hb] = rh.w;
            // U float4 covers gate ug, j cols 4*ujp2..+3 -> jp 2*ujp2, 2*ujp2+1
            {
                u64* arr0 = (ug < 2) ? &UsA[buf][uk][2 * ujp2][ug]
                                     : &UsB[buf][uk][2 * ujp2][ug - 2];
                u64* arr1 = (ug < 2) ? &UsA[buf][uk][2 * ujp2 + 1][ug]
                                     : &UsB[buf][uk][2 * ujp2 + 1][ug - 2];
                *(float2*)arr0 = make_float2(ru.x, ru.y);
                *(float2*)arr1 = make_float2(ru.z, ru.w);
            }
            __syncthreads();

            if (c + 1 < NCHUNK) {
                const int k0 = (c + 1) * 16;
                rh = __ldcg((const float4*)(hsrc + k0));
                ru = *(const float4*)(ubase + (size_t)k0 * G4);
            }

            #pragma unroll
            for (int k = 0; k < 16; k++) {
                float2 hf = *(const float2*)&Hs[buf][k][bm * 2];
                u64 h0 = pack2_(hf.x);
                u64 h1 = pack2_(hf.y);
                ulonglong2 ua = *(const ulonglong2*)&UsA[buf][k][jp][0];
                ulonglong2 ub2 = *(const ulonglong2*)&UsB[buf][k][jp][0];
                acc[0][0] = fma2_(h0, ua.x,  acc[0][0]);
                acc[0][1] = fma2_(h0, ua.y,  acc[0][1]);
                acc[0][2] = fma2_(h0, ub2.x, acc[0][2]);
                acc[0][3] = fma2_(h0, ub2.y, acc[0][3]);
                acc[1][0] = fma2_(h1, ua.x,  acc[1][0]);
                acc[1][1] = fma2_(h1, ua.y,  acc[1][1]);
                acc[1][2] = fma2_(h1, ub2.x, acc[1][2]);
                acc[1][3] = fma2_(h1, ub2.y, acc[1][3]);
            }
            // single barrier per chunk: the next write targets buf^1, whose
            // readers are guaranteed done once the next barrier is passed.
        }

        // epilogue: unpack (j_even, j_odd) per gate, gates -> c -> h
        #pragma unroll
        for (int r = 0; r < 2; r++) {
            const int b = 2 * bm + r;
            float zi0, zi1, zf0, zf1, zg0, zg1, zo0, zo1;
            unpack2_(acc[r][0], zi0, zi1);
            unpack2_(acc[r][1], zf0, zf1);
            unpack2_(acc[r][2], zg0, zg1);
            unpack2_(acc[r][3], zo0, zo1);
            zi0 += xzv[r][0].x; zi1 += xzv[r][0].y;
            zf0 += xzv[r][1].x; zf1 += xzv[r][1].y;
            zg0 += xzv[r][2].x; zg1 += xzv[r][2].y;
            zo0 += xzv[r][3].x; zo1 += xzv[r][3].y;

            float cc0 = sigmoidf_(zf0) * c_reg[r][0] + sigmoidf_(zi0) * tanhf(zg0);
            float cc1 = sigmoidf_(zf1) * c_reg[r][1] + sigmoidf_(zi1) * tanhf(zg1);
            c_reg[r][0] = cc0;
            c_reg[r][1] = cc1;
            float2 hv = make_float2(sigmoidf_(zo0) * tanhf(cc0),
                                    sigmoidf_(zo1) * tanhf(cc1));

            if (s + 1 < TT)  // last step's h has no reader
                __stcg((float2*)&g_h[wbuf][dir][b][je], hv);
            __stcs((float2*)&out[(size_t)b * (TT * 2 * HH) + (size_t)t * (2 * HH)
                                 + dir * HH + je], hv);
        }

        // all h[wbuf] writes must be visible before any block starts s+1
        grid_barrier(NBLK * (unsigned)(s + 2));
    }
}

// ---------------------------------------------------------------------------
// Launch: reset barrier -> input GEMM -> ONE persistent recurrence kernel.
// ---------------------------------------------------------------------------
extern "C" void kernel_launch(void* const* d_in, const int* in_sizes, int n_in,
                              void* d_out, int out_size)
{
    const float* x  = (const float*)d_in[0];
    const float* Wf = (const float*)d_in[1];
    const float* Uf = (const float*)d_in[2];
    const float* bf = (const float*)d_in[3];
    const float* Wb = (const float*)d_in[4];
    const float* Ub = (const float*)d_in[5];
    const float* bb = (const float*)d_in[6];
    float* out = (float*)d_out;

    reset_kernel<<<1, 1>>>();

    dim3 ggrid(64, 128);
    input_gemm_kernel<<<ggrid, 256>>>(x, Wf, bf, Wb, bb);

    persistent_lstm_kernel<<<NBLK, 256>>>(Uf, Ub, out);
}

// round 14
// speedup vs baseline: 1.5146x; 1.5146x over previous
#include <cuda_runtime.h>
#include <math.h>

// Problem constants
#define BB   64
#define TT   256
#define DD   1024
#define HH   1024
#define G4   4096      // 4*H
#define MROWS (BB*TT)  // 16384
#define NBLK 128u      // persistent grid size (<= SM count, all co-resident)

// Scratch (static device allocations — allowed; no cudaMalloc anywhere)
__device__ float g_xz[2][MROWS][G4];       // input projections, fwd/bwd (536 MB)
__device__ float g_h[2][2][BB][HH];        // h state, [buffer][dir][b][j]
__device__ unsigned g_bar;                 // grid barrier counter

// ---------------------------------------------------------------------------
// Packed f32x2 helpers (used by the recurrence)
// ---------------------------------------------------------------------------
typedef unsigned long long u64;

__device__ __forceinline__ u64 fma2_(u64 a, u64 b, u64 c) {
    u64 d;
    asm("fma.rn.f32x2 %0, %1, %2, %3;" : "=l"(d) : "l"(a), "l"(b), "l"(c));
    return d;
}
__device__ __forceinline__ u64 pack2_(float v) {   // (v, v)
    u64 d;
    asm("mov.b64 %0, {%1, %1};" : "=l"(d) : "r"(__float_as_uint(v)));
    return d;
}
__device__ __forceinline__ void unpack2_(u64 v, float& lo, float& hi) {
    asm("mov.b64 {%0, %1}, %2;" : "=f"(lo), "=f"(hi) : "l"(v));
}

// tf32 convert (round-to-nearest)
__device__ __forceinline__ unsigned tf32_(float v) {
    unsigned r;
    asm("cvt.rna.tf32.f32 %0, %1;" : "=r"(r) : "f"(v));
    return r;
}

// m16n8k8 tf32 mma: D = A*B + D (A row-major, B col-major fragments)
__device__ __forceinline__ void mma_tf32_(float* c, const unsigned* a, const unsigned* b) {
    asm volatile(
        "mma.sync.aligned.m16n8k8.row.col.f32.tf32.tf32.f32 "
        "{%0,%1,%2,%3}, {%4,%5,%6,%7}, {%8,%9}, {%0,%1,%2,%3};"
        : "+f"(c[0]), "+f"(c[1]), "+f"(c[2]), "+f"(c[3])
        : "r"(a[0]), "r"(a[1]), "r"(a[2]), "r"(a[3]), "r"(b[0]), "r"(b[1]));
}

// ---------------------------------------------------------------------------
// Reset the grid-barrier counter (fresh on every graph replay).
// ---------------------------------------------------------------------------
__global__ void reset_kernel() { g_bar = 0u; }

// ---------------------------------------------------------------------------
// Grid-wide barrier for a fully co-resident grid (CG grid.sync pattern).
// ---------------------------------------------------------------------------
__device__ __forceinline__ void grid_barrier(unsigned target) {
    __syncthreads();
    if (threadIdx.x == 0) {
        unsigned* p = &g_bar;
        asm volatile("red.release.gpu.global.add.u32 [%0], 1;" :: "l"(p) : "memory");
        unsigned v;
        for (;;) {
            asm volatile("ld.acquire.gpu.global.u32 %0, [%1];" : "=r"(v) : "l"(p) : "memory");
            if (v >= target) break;
            __nanosleep(32);
        }
    }
    __syncthreads();
}

// ---------------------------------------------------------------------------
// Input projection on TENSOR CORES (tf32 warp mma).
// g_xz[dir][b*T+t][g] = sum_d x[b,t,d] * W[d,g] + bias[g]
// BM=128, BN=128, BK=16. 8 warps = 2(M) x 4(N); each warp 64x32 via 4x4
// m16n8k8 tiles. A in SMEM m-major with k/(k+4) interleaved pairs so each
// A-fragment half is one LDS.64; B k-major, row padded to 132 words.
// tf32 conversion (cvt.rna) applied once at staging. Double-buffered SMEM,
// single barrier per chunk. fp32 accumulate; epilogue adds bias, streams out.
// grid = (64, 128): blockIdx.x = dir*32 + ntile, blockIdx.y = mtile
// ---------------------------------------------------------------------------
#define BPAD 132

__global__ __launch_bounds__(256)
void input_gemm_kernel(const float* __restrict__ x,
                       const float* __restrict__ Wf, const float* __restrict__ bf,
                       const float* __restrict__ Wb, const float* __restrict__ bb)
{
    const int dir = blockIdx.x >> 5;
    const int ntb = blockIdx.x & 31;
    const int m0  = blockIdx.y * 128;
    const int n0  = ntb * 128;
    const float* __restrict__ W    = dir ? Wb : Wf;
    const float* __restrict__ bias = dir ? bb : bf;

    __shared__ unsigned As[2][128][16];    // [buf][m][slab*8 + pairpos] (tf32 bits)
    __shared__ unsigned Bs[2][16][BPAD];   // [buf][k][n] (tf32 bits)

    const int tid  = threadIdx.x;
    const int wid  = tid >> 5;
    const int lane = tid & 31;
    const int g    = lane >> 2;     // 0..7
    const int t4   = lane & 3;      // 0..3

    const int mw = (wid >> 2) * 64; // warp m origin within tile
    const int nw = (wid & 3) * 32;  // warp n origin within tile

    // staging indices
    const int arow  = tid >> 1;          // 0..127
    const int aslab = tid & 1;           // k-slab 0/1 (8 k each)
    const int brow  = tid >> 4;          // 0..15
    const int bcol  = (tid & 15) * 8;    // 0..120

    float acc[4][4][4];
    #pragma unroll
    for (int mt = 0; mt < 4; mt++)
        #pragma unroll
        for (int nt = 0; nt < 4; nt++)
            #pragma unroll
            for (int q = 0; q < 4; q++) acc[mt][nt][q] = 0.0f;

    const float* __restrict__ aptr = x + (size_t)(m0 + arow) * DD + aslab * 8;
    const float* __restrict__ bptr = W + (size_t)brow * G4 + n0 + bcol;

    // prefetch chunk 0
    float4 av0 = *(const float4*)(aptr);
    float4 av1 = *(const float4*)(aptr + 4);
    float4 bv0 = *(const float4*)(bptr);
    float4 bv1 = *(const float4*)(bptr + 4);

    const int NCHUNK = DD / 16;  // 64
    for (int c = 0; c < NCHUNK; c++) {
        const int buf = c & 1;
        // A: interleave (k, k+4) pairs: positions 2*(k%4), 2*(k%4)+1
        {
            uint4 p0 = make_uint4(tf32_(av0.x), tf32_(av1.x), tf32_(av0.y), tf32_(av1.y));
            uint4 p1 = make_uint4(tf32_(av0.z), tf32_(av1.z), tf32_(av0.w), tf32_(av1.w));
            *(uint4*)&As[buf][arow][aslab * 8 + 0] = p0;
            *(uint4*)&As[buf][arow][aslab * 8 + 4] = p1;
        }
        // B: natural k-major
        {
            uint4 q0 = make_uint4(tf32_(bv0.x), tf32_(bv0.y), tf32_(bv0.z), tf32_(bv0.w));
            uint4 q1 = make_uint4(tf32_(bv1.x), tf32_(bv1.y), tf32_(bv1.z), tf32_(bv1.w));
            *(uint4*)&Bs[buf][brow][bcol]     = q0;
            *(uint4*)&Bs[buf][brow][bcol + 4] = q1;
        }
        __syncthreads();

        if (c + 1 < NCHUNK) {
            const int k0 = (c + 1) * 16;
            av0 = *(const float4*)(aptr + k0);
            av1 = *(const float4*)(aptr + k0 + 4);
            bv0 = *(const float4*)(bptr + (size_t)k0 * G4);
            bv1 = *(const float4*)(bptr + (size_t)k0 * G4 + 4);
        }

        #pragma unroll
        for (int slab = 0; slab < 2; slab++) {
            unsigned afrag[4][4];
            #pragma unroll
            for (int mt = 0; mt < 4; mt++) {
                // pairpos 2*t4 holds k=t4, 2*t4+1 holds k=t4+4
                uint2 lo = *(const uint2*)&As[buf][mw + mt * 16 + g][slab * 8 + 2 * t4];
                uint2 hi = *(const uint2*)&As[buf][mw + mt * 16 + g + 8][slab * 8 + 2 * t4];
                afrag[mt][0] = lo.x;  // (row g,   k=t4)
                afrag[mt][1] = hi.x;  // (row g+8, k=t4)
                afrag[mt][2] = lo.y;  // (row g,   k=t4+4)
                afrag[mt][3] = hi.y;  // (row g+8, k=t4+4)
            }
            unsigned bfrag[4][2];
            #pragma unroll
            for (int nt = 0; nt < 4; nt++) {
                bfrag[nt][0] = Bs[buf][slab * 8 + t4][nw + nt * 8 + g];
                bfrag[nt][1] = Bs[buf][slab * 8 + t4 + 4][nw + nt * 8 + g];
            }
            #pragma unroll
            for (int mt = 0; mt < 4; mt++)
                #pragma unroll
                for (int nt = 0; nt < 4; nt++)
                    mma_tf32_(acc[mt][nt], afrag[mt], bfrag[nt]);
        }
        // single barrier per chunk (R8-proven protocol)
    }

    // epilogue: bias + streaming float2 stores
    #pragma unroll
    for (int nt = 0; nt < 4; nt++) {
        const int col = n0 + nw + nt * 8 + 2 * t4;
        const float2 bias2 = *(const float2*)&bias[col];
        #pragma unroll
        for (int mt = 0; mt < 4; mt++) {
            const int r0 = m0 + mw + mt * 16 + g;
            const int r1 = r0 + 8;
            float2 v0 = make_float2(acc[mt][nt][0] + bias2.x, acc[mt][nt][1] + bias2.y);
            float2 v1 = make_float2(acc[mt][nt][2] + bias2.x, acc[mt][nt][3] + bias2.y);
            __stcs((float2*)&g_xz[dir][r0][col], v0);
            __stcs((float2*)&g_xz[dir][r1][col], v1);
        }
    }
}

// ---------------------------------------------------------------------------
// Persistent BiLSTM recurrence — EXACT R8 version (best measured: 36.7us/step).
// ---------------------------------------------------------------------------
__device__ __forceinline__ float sigmoidf_(float v) {
    return 1.0f / (1.0f + __expf(-v));
}

#define HSPAD 68   // row pad (words); multiple of 4 keeps 16B alignment

__global__ __launch_bounds__(256, 1)
void persistent_lstm_kernel(const float* __restrict__ Uf,
                            const float* __restrict__ Ub,
                            float* __restrict__ out)
{
    const int bx  = blockIdx.x;
    const int dir = bx >> 6;
    const int j0  = (bx & 63) * 16;
    const float* __restrict__ U = dir ? Ub : Uf;

    __shared__ float Hs[2][16][HSPAD];   // [buf][k][b]
    __shared__ float Us[2][16][HSPAD];   // [buf][k][jj*4 + gate]

    const int tid = threadIdx.x;
    const int tm = tid >> 4;       // 0..15 -> rows (b) tm*4..+3
    const int tn = tid & 15;       // j lane (jj)
    const int j  = j0 + tn;

    const int hb  = tid >> 2;          // 0..63
    const int hk4 = (tid & 3) * 4;     // 0,4,8,12
    const int ukk = tid >> 4;          // 0..15
    const int ulane = tid & 15;

    const float* __restrict__ ubase = U + (size_t)ukk * G4 + j0 + ulane;
    const float* __restrict__ hsrc0 = &g_h[0][dir][hb][hk4];
    const float* __restrict__ hsrc1 = &g_h[1][dir][hb][hk4];

    // ---- phase 0: zero the s=0 read buffer for this block's slice; c -> regs
    #pragma unroll
    for (int r = 0; r < 4; r++)
        __stcg(&g_h[0][dir][tm * 4 + r][j], 0.0f);
    float c_reg[4] = {0.0f, 0.0f, 0.0f, 0.0f};
    grid_barrier(NBLK);

    // ---- 256 timesteps
    for (int s = 0; s < TT; s++) {
        const int t    = dir ? (TT - 1 - s) : s;
        const int rb   = s & 1;
        const int wbuf = rb ^ 1;
        const float* __restrict__ hsrc = rb ? hsrc1 : hsrc0;

        // prefetch xz for the epilogue (read-once stream: evict-first)
        float xzv[4][4];
        #pragma unroll
        for (int r = 0; r < 4; r++) {
            const int b = tm * 4 + r;
            const float* xz = &g_xz[dir][(size_t)b * TT + t][j];
            xzv[r][0] = __ldcs(xz);
            xzv[r][1] = __ldcs(xz + HH);
            xzv[r][2] = __ldcs(xz + 2 * HH);
            xzv[r][3] = __ldcs(xz + 3 * HH);
        }

        u64 acc2[2][4];   // [row-pair][gate]
        #pragma unroll
        for (int r2 = 0; r2 < 2; r2++)
            #pragma unroll
            for (int q = 0; q < 4; q++) acc2[r2][q] = 0ull;

        // prefetch chunk 0 (h via .cg: L2-coherent across SMs)
        float4 rh = __ldcg((const float4*)hsrc);
        float4 ru = make_float4(ubase[0], ubase[HH], ubase[2 * HH], ubase[3 * HH]);

        const int NCHUNK = HH / 16;  // 64
        for (int c = 0; c < NCHUNK; c++) {
            const int buf = c & 1;
            Hs[buf][hk4 + 0][hb] = rh.x;
            Hs[buf][hk4 + 1][hb] = rh.y;
            Hs[buf][hk4 + 2][hb] = rh.z;
            Hs[buf][hk4 + 3][hb] = rh.w;
            *(float4*)&Us[buf][ukk][ulane * 4] = ru;
            __syncthreads();

            if (c + 1 < NCHUNK) {
                const int k0 = (c + 1) * 16;
                rh = __ldcg((const float4*)(hsrc + k0));
                const float* up = ubase + (size_t)k0 * G4;
                ru = make_float4(up[0], up[HH], up[2 * HH], up[3 * HH]);
            }

            #pragma unroll
            for (int k = 0; k < 16; k++) {
                ulonglong2 hp = *(const ulonglong2*)&Hs[buf][k][tm * 4];
                float4 u4 = *(const float4*)&Us[buf][k][tn * 4];
                u64 ui = pack2_(u4.x);
                u64 uf = pack2_(u4.y);
                u64 ug = pack2_(u4.z);
                u64 uo = pack2_(u4.w);
                acc2[0][0] = fma2_(hp.x, ui, acc2[0][0]);
                acc2[0][1] = fma2_(hp.x, uf, acc2[0][1]);
                acc2[0][2] = fma2_(hp.x, ug, acc2[0][2]);
                acc2[0][3] = fma2_(hp.x, uo, acc2[0][3]);
                acc2[1][0] = fma2_(hp.y, ui, acc2[1][0]);
                acc2[1][1] = fma2_(hp.y, uf, acc2[1][1]);
                acc2[1][2] = fma2_(hp.y, ug, acc2[1][2]);
                acc2[1][3] = fma2_(hp.y, uo, acc2[1][3]);
            }
        }

        // unpack accumulators
        float accf[4][4];
        #pragma unroll
        for (int r2 = 0; r2 < 2; r2++)
            #pragma unroll
            for (int q = 0; q < 4; q++)
                unpack2_(acc2[r2][q], accf[2 * r2][q], accf[2 * r2 + 1][q]);

        #pragma unroll
        for (int r = 0; r < 4; r++) {
            const int b = tm * 4 + r;
            float zi = accf[r][0] + xzv[r][0];
            float zf = accf[r][1] + xzv[r][1];
            float zg = accf[r][2] + xzv[r][2];
            float zo = accf[r][3] + xzv[r][3];

            float gi = sigmoidf_(zi);
            float gf = sigmoidf_(zf);
            float gg = tanhf(zg);
            float go = sigmoidf_(zo);

            float cc = gf * c_reg[r] + gi * gg;
            c_reg[r] = cc;
            float h = go * tanhf(cc);

            __stcg(&g_h[wbuf][dir][b][j], h);
            __stcs(&out[(size_t)b * (TT * 2 * HH) + (size_t)t * (2 * HH) + dir * HH + j], h);
        }

        // all h[wbuf] writes must be visible before any block starts step s+1
        grid_barrier(NBLK * (unsigned)(s + 2));
    }
}

// ---------------------------------------------------------------------------
// Launch: reset barrier -> tf32 input GEMM -> ONE persistent recurrence kernel.
// ---------------------------------------------------------------------------
extern "C" void kernel_launch(void* const* d_in, const int* in_sizes, int n_in,
                              void* d_out, int out_size)
{
    const float* x  = (const float*)d_in[0];
    const float* Wf = (const float*)d_in[1];
    const float* Uf = (const float*)d_in[2];
    const float* bf = (const float*)d_in[3];
    const float* Wb = (const float*)d_in[4];
    const float* Ub = (const float*)d_in[5];
    const float* bb = (const float*)d_in[6];
    float* out = (float*)d_out;

    reset_kernel<<<1, 1>>>();

    dim3 ggrid(64, 128);
    input_gemm_kernel<<<ggrid, 256>>>(x, Wf, bf, Wb, bb);

    persistent_lstm_kernel<<<NBLK, 256>>>(Uf, Ub, out);
}